// round 7
// baseline (speedup 1.0000x reference)
#include <cuda_runtime.h>
#include <math.h>

// IN_FEATURES=128, UNITS=512, BATCH=2048, out = [x (2048*128) ; logdet (2048)]
#define R        8       // rows per CTA
#define RP       8       // per-unit row stride (floats) - exact, conflict-free
#define THREADS  512
#define NBLK     256     // 2048 / 8  -> 2 CTAs per SM

typedef unsigned long long ull;

__device__ float g_W1c[128 * 512];   // [i][p]
__device__ float g_W2t[512 * 512];   // [p][q]
__device__ float g_W3t[512 * 256];   // [q][o]
__device__ float g_A1init[512];      // b1 permuted

__device__ __forceinline__ int posOf(int k) {
    int d = k % 127;
    int j = k / 127;
    return d * 4 + (d < 4 ? d : 4) + j;
}
__device__ __forceinline__ int origOf(int q) {
    int d, j;
    if (q < 20) { d = q / 5; j = q - d * 5; }
    else        { d = 4 + ((q - 20) >> 2); j = (q - 20) & 3; }
    return d + 127 * j;
}

// ---------------- prologue: mask + permute + transpose ----------------
__global__ void k_transform(const float* __restrict__ W1, const float* __restrict__ b1,
                            const float* __restrict__ W2, const float* __restrict__ W3,
                            const float* __restrict__ m1, const float* __restrict__ m2,
                            const float* __restrict__ m3) {
    int idx = blockIdx.x * blockDim.x + threadIdx.x;
    int stride = gridDim.x * blockDim.x;
    for (int t = idx; t < 512 * 128; t += stride) {
        int k = t >> 7, i = t & 127;
        g_W1c[i * 512 + posOf(k)] = W1[t] * m1[t];
    }
    for (int t = idx; t < 512 * 512; t += stride) {
        int m = t >> 9, k = t & 511;
        g_W2t[posOf(k) * 512 + posOf(m)] = W2[t] * m2[t];
    }
    for (int t = idx; t < 256 * 512; t += stride) {
        int o = t >> 9, m = t & 511;
        g_W3t[posOf(m) * 256 + o] = W3[t] * m3[t];
    }
    for (int t = idx; t < 512; t += stride)
        g_A1init[posOf(t)] = b1[t];
}

// ---- packed f32x2 helpers ----
__device__ __forceinline__ ull dup2(float w) {
    ull r; asm("mov.b64 %0, {%1, %1};" : "=l"(r) : "f"(w)); return r;
}
__device__ __forceinline__ float2 u2f(ull v) {
    float2 f; asm("mov.b64 {%0, %1}, %2;" : "=f"(f.x), "=f"(f.y) : "l"(v)); return f;
}
#define PFMA(acc, w, v) asm("fma.rn.f32x2 %0, %1, %2, %0;" : "+l"(acc) : "l"(w), "l"(v))
__device__ __forceinline__ void addp(ull& a, ull b) {
    asm("add.rn.f32x2 %0, %0, %1;" : "+l"(a) : "l"(b));
}
// acc[0..3] (8 rows) += w * vec8 (2 x LDS.128, broadcast)
__device__ __forceinline__ void fma4x2(ull* acc, const float* base, float w) {
    ull ww = dup2(w);
    const ulonglong2* v = (const ulonglong2*)base;
    ulonglong2 a = v[0], b = v[1];
    PFMA(acc[0], ww, a.x); PFMA(acc[1], ww, a.y);
    PFMA(acc[2], ww, b.x); PFMA(acc[3], ww, b.y);
}

// ---------------- main persistent kernel: 256 CTAs x 8 rows, 2 CTAs/SM ----------------
__global__ void __launch_bounds__(THREADS, 2)
k_main(const float* __restrict__ u, const float* __restrict__ b2,
       const float* __restrict__ b3, float* __restrict__ out) {
    extern __shared__ float sm[];
    float* A1  = sm;                 // 512*RP
    float* A2  = A1 + 512 * RP;
    float* DH1 = A2 + 512 * RP;
    float* DH2 = DH1 + 512 * RP;
    float* Z   = DH2 + 512 * RP;     // 256*RP
    float* us  = Z + 256 * RP;       // 128*8 u transposed [i][r]
    float* xs  = us + 128 * R;       // 128*8 x transposed [i][r]

    const int tid  = threadIdx.x;
    const int lane = tid & 31;
    const int row0 = blockIdx.x * R;

    // ---- inline init: x=0 forward pass ----
    for (int t = tid; t < R * 128; t += THREADS) {
        int r = t >> 7, c = t & 127;
        us[c * R + r] = u[(row0 + r) * 128 + c];
    }
    float a1v = g_A1init[tid];
    DH1[tid] = fmaxf(a1v, 0.f);
    __syncthreads();
    float a2v;
    {
        float acc = b2[origOf(tid)];
#pragma unroll 4
        for (int p = 0; p < 512; ++p) acc = fmaf(g_W2t[p * 512 + tid], DH1[p], acc);
        a2v = acc;
        DH2[tid] = fmaxf(acc, 0.f);
    }
    __syncthreads();
    float zv = 0.f;
    if (tid < 256) {
        float a = b3[tid];
#pragma unroll 4
        for (int q = 0; q < 512; ++q) a = fmaf(g_W3t[q * 256 + tid], DH2[q], a);
        zv = a;
    }
    __syncthreads();
#pragma unroll
    for (int r = 0; r < R; ++r) { A1[tid * RP + r] = a1v; A2[tid * RP + r] = a2v; }
    if (tid < 256) {
#pragma unroll
        for (int r = 0; r < R; ++r) Z[tid * RP + r] = zv;
    }
    float ldacc = 0.f;
    __syncthreads();

    for (int i = 0; i < 128; ++i) {
        // ---- (a) each warp computes x_i redundantly (no barrier) ----
        float xval = 0.f;
        if (lane < R) {
            float mu = Z[i * RP + lane];
            float sg = Z[(128 + i) * RP + lane];
            xval = us[i * R + lane] * __expf(sg) + mu;
            xs[i * R + lane] = xval;       // identical duplicate writes
            if (tid < R) ldacc += sg;
        }
        if (i == 127) break;

        const int s    = 4 * i + (i < 4 ? i : 4);
        const int cols = 512 - s;

        // ---- (c) layer-1 suffix update ----
        {
            int r = tid & 7;
            float x = __shfl_sync(0xffffffffu, xval, r);
            for (int p = s + (tid >> 3); p < 512; p += THREADS / 8) {
                float w   = g_W1c[i * 512 + p];
                float old = A1[p * RP + r];
                float nw  = fmaf(w, x, old);
                A1[p * RP + r]  = nw;
                DH1[p * RP + r] = fmaxf(nw, 0.f) - fmaxf(old, 0.f);
            }
        }
        __syncthreads();

        // ---- (d) A2[q,:] += sum_p W2t[p][q] * DH1[p,:] ----
        if (cols > 256) {
            if (tid < cols) {
                int q = s + tid;
                ull acc[4];
#pragma unroll
                for (int k = 0; k < 4; ++k) acc[k] = 0ull;
#pragma unroll 4
                for (int p = s; p < 512; ++p)
                    fma4x2(acc, DH1 + p * RP, g_W2t[p * 512 + q]);
#pragma unroll
                for (int k = 0; k < 4; ++k) {
                    float2 a = u2f(acc[k]);
                    float o0 = A2[q * RP + 2 * k],     n0 = o0 + a.x;
                    float o1 = A2[q * RP + 2 * k + 1], n1 = o1 + a.y;
                    A2[q * RP + 2 * k]      = n0;
                    A2[q * RP + 2 * k + 1]  = n1;
                    DH2[q * RP + 2 * k]     = fmaxf(n0, 0.f) - fmaxf(o0, 0.f);
                    DH2[q * RP + 2 * k + 1] = fmaxf(n1, 0.f) - fmaxf(o1, 0.f);
                }
            }
        } else {
            int active = 2 * cols;
            if (tid < ((active + 31) & ~31)) {
                int j    = tid >> 1;
                int half = tid & 1;
                int q    = s + (j < cols ? j : cols - 1);
                int mid  = s + (cols >> 1);
                int p0   = half ? mid : s;
                int p1   = half ? 512 : mid;
                ull acc[4];
#pragma unroll
                for (int k = 0; k < 4; ++k) acc[k] = 0ull;
#pragma unroll 4
                for (int p = p0; p < p1; ++p)
                    fma4x2(acc, DH1 + p * RP, g_W2t[p * 512 + q]);
#pragma unroll
                for (int k = 0; k < 4; ++k)
                    addp(acc[k], __shfl_xor_sync(0xffffffffu, acc[k], 1));
                if (half == 0 && j < cols) {
#pragma unroll
                    for (int k = 0; k < 4; ++k) {
                        float2 a = u2f(acc[k]);
                        float o0 = A2[q * RP + 2 * k],     n0 = o0 + a.x;
                        float o1 = A2[q * RP + 2 * k + 1], n1 = o1 + a.y;
                        A2[q * RP + 2 * k]      = n0;
                        A2[q * RP + 2 * k + 1]  = n1;
                        DH2[q * RP + 2 * k]     = fmaxf(n0, 0.f) - fmaxf(o0, 0.f);
                        DH2[q * RP + 2 * k + 1] = fmaxf(n1, 0.f) - fmaxf(o1, 0.f);
                    }
                }
            }
        }
        __syncthreads();

        // ---- (e) z update: 2 threads per output column ----
        {
            int hc     = 127 - i;
            int ocnt   = 2 * hc;
            int active = 2 * ocnt;
            if (tid < ((active + 31) & ~31)) {
                int j    = tid >> 1;
                int half = tid & 1;
                int jj   = (j < ocnt) ? j : ocnt - 1;
                int o    = (jj < hc) ? (i + 1 + jj) : (129 + i + (jj - hc));
                int mid  = s + (cols >> 1);
                int q0   = half ? mid : s;
                int q1   = half ? 512 : mid;
                ull acc[4];
#pragma unroll
                for (int k = 0; k < 4; ++k) acc[k] = 0ull;
#pragma unroll 4
                for (int q = q0; q < q1; ++q)
                    fma4x2(acc, DH2 + q * RP, g_W3t[q * 256 + o]);
#pragma unroll
                for (int k = 0; k < 4; ++k)
                    addp(acc[k], __shfl_xor_sync(0xffffffffu, acc[k], 1));
                if (half == 0 && j < ocnt) {
#pragma unroll
                    for (int k = 0; k < 4; ++k) {
                        float2 a = u2f(acc[k]);
                        Z[o * RP + 2 * k]     += a.x;
                        Z[o * RP + 2 * k + 1] += a.y;
                    }
                }
            }
        }
        __syncthreads();
    }

    __syncthreads();
    for (int t = tid; t < R * 128; t += THREADS) {
        int r = t >> 7, c = t & 127;
        out[(row0 + r) * 128 + c] = xs[c * R + r];
    }
    if (tid < R) out[2048 * 128 + row0 + tid] = ldacc;
}

extern "C" void kernel_launch(void* const* d_in, const int* in_sizes, int n_in,
                              void* d_out, int out_size) {
    const float* u  = (const float*)d_in[0];
    const float* W1 = (const float*)d_in[1];
    const float* b1 = (const float*)d_in[2];
    const float* W2 = (const float*)d_in[3];
    const float* b2 = (const float*)d_in[4];
    const float* W3 = (const float*)d_in[5];
    const float* b3 = (const float*)d_in[6];
    const float* m1 = (const float*)d_in[7];
    const float* m2 = (const float*)d_in[8];
    const float* m3 = (const float*)d_in[9];
    float* out = (float*)d_out;

    const size_t smem = (size_t)(512 * RP * 4 + 256 * RP + 128 * R * 2) * sizeof(float); // 81920 B
    cudaFuncSetAttribute(k_main, cudaFuncAttributeMaxDynamicSharedMemorySize, (int)smem);

    k_transform<<<256, 256>>>(W1, b1, W2, W3, m1, m2, m3);
    k_main<<<NBLK, THREADS, smem>>>(u, b2, b3, out);
}

// round 8
// speedup vs baseline: 9.1242x; 9.1242x over previous
#include <cuda_runtime.h>
#include <math.h>

// IN_FEATURES=128, UNITS=512, BATCH=2048, out = [x (2048*128) ; logdet (2048)]
// O(n^2) sequential MADE inverse: each hidden unit computed exactly once when
// its inputs are final (degree-sorted permutation => stable prefixes).
#define THREADS 512
#define PH      520      // padded row stride for h1T/h2T (floats)
#define XS      132      // padded row stride for xs/us

typedef unsigned long long ull;

// ---- device scratch ----
__device__ float g_W1p[512 * 128];      // [p][j]   masked W1, hidden permuted
__device__ float g_W2q[512 * 512];      // [q][p]   masked W2, both permuted
__device__ float g_W3z[128 * 512 * 2];  // [o][q]{mu,sig} interleaved pairs
__device__ float g_b1p[512];
__device__ float g_b2p[512];

__device__ __forceinline__ int posOf(int k) {
    int d = k % 127;
    int j = k / 127;
    return d * 4 + (d < 4 ? d : 4) + j;
}

// ---------------- prologue: mask + permute + repack ----------------
__global__ void k_transform(const float* __restrict__ W1, const float* __restrict__ b1,
                            const float* __restrict__ W2, const float* __restrict__ b2,
                            const float* __restrict__ W3,
                            const float* __restrict__ m1, const float* __restrict__ m2,
                            const float* __restrict__ m3) {
    int idx = blockIdx.x * blockDim.x + threadIdx.x;
    int stride = gridDim.x * blockDim.x;
    // W1 [512,128] -> g_W1p[pos(k)][i]
    for (int t = idx; t < 512 * 128; t += stride) {
        int k = t >> 7, i = t & 127;
        g_W1p[posOf(k) * 128 + i] = W1[t] * m1[t];
    }
    // W2 [512,512] (m,k) -> g_W2q[pos(m)][pos(k)]
    for (int t = idx; t < 512 * 512; t += stride) {
        int m = t >> 9, k = t & 511;
        g_W2q[posOf(m) * 512 + posOf(k)] = W2[t] * m2[t];
    }
    // W3 [256,512] (o,m) -> g_W3z[o][pos(m)][{mu=o, sig=o+128}]
    for (int t = idx; t < 256 * 512; t += stride) {
        int o = t >> 9, m = t & 511;
        float v = W3[t] * m3[t];
        int q = posOf(m);
        if (o < 128) g_W3z[(o * 512 + q) * 2]            = v;
        else         g_W3z[((o - 128) * 512 + q) * 2 + 1] = v;
    }
    for (int t = idx; t < 512; t += stride) {
        g_b1p[posOf(t)] = b1[t];
        g_b2p[posOf(t)] = b2[t];
    }
}

// ---- packed f32x2 helpers ----
__device__ __forceinline__ ull dup2(float w) {
    ull r; asm("mov.b64 %0, {%1, %1};" : "=l"(r) : "f"(w)); return r;
}
__device__ __forceinline__ float2 u2f(ull v) {
    float2 f; asm("mov.b64 {%0, %1}, %2;" : "=f"(f.x), "=f"(f.y) : "l"(v)); return f;
}
#define PFMA(acc, w, v) asm("fma.rn.f32x2 %0, %1, %2, %0;" : "+l"(acc) : "l"(w), "l"(v))
__device__ __forceinline__ void addp(ull& a, ull b) {
    asm("add.rn.f32x2 %0, %0, %1;" : "+l"(a) : "l"(b));
}

// ---------------- main kernel: 128 CTAs x 16 rows ----------------
__global__ void __launch_bounds__(THREADS, 1)
k_main(const float* __restrict__ u, const float* __restrict__ b3,
       float* __restrict__ out) {
    extern __shared__ float sm[];
    float* h1T = sm;                  // [16][PH]  relu'd layer-1 units
    float* h2T = h1T + 16 * PH;       // [16][PH]  relu'd layer-2 units
    float* xs  = h2T + 16 * PH;       // [16][XS]  x transposed [r][i]
    float* us  = xs + 16 * XS;        // [16][XS]  u transposed [r][i]

    const int tid  = threadIdx.x;
    const int lane = tid & 31;
    const int w    = tid >> 5;        // warp id = row for Z phase
    const int row0 = blockIdx.x * 16;

    // stage u transposed
    for (int t = tid; t < 16 * 128; t += THREADS) {
        int r = t >> 7, c = t & 127;
        us[r * XS + c] = u[(row0 + r) * 128 + c];
    }
    float ldacc = 0.f;
    __syncthreads();

    for (int i = 0; i < 128; ++i) {
        const int s_i = 4 * i + (i < 4 ? i : 4);   // prefix length (deg < i)

        // ---- Z phase: warp w computes (mu_i, sigma_i, x_i) for row w ----
        {
            const int r = w;
            ull acc = 0ull;
            const ull* wz = (const ull*)g_W3z + (size_t)i * 512;
            const float* hr = h2T + r * PH;
            for (int q = lane; q < s_i; q += 32) {
                ull wv = wz[q];                      // {w_mu, w_sig} 8B coalesced
                PFMA(acc, wv, dup2(hr[q]));
            }
#pragma unroll
            for (int off = 16; off >= 1; off >>= 1)
                addp(acc, __shfl_xor_sync(0xffffffffu, acc, off));
            if (lane == 0) {
                float2 ms = u2f(acc);
                float sg = ms.y + b3[i + 128];
                float x  = us[r * XS + i] * __expf(sg) + (ms.x + b3[i]);
                xs[r * XS + i] = x;
                ldacc += sg;
            }
        }
        __syncthreads();
        if (i == 127) break;

        const int s_n = 4 * (i + 1) + (i + 1 < 4 ? i + 1 : 4);
        const int nd  = s_n - s_i;                  // 5 (i<4) or 4

        // ---- H1 phase: new layer-1 columns p in [s_i, s_n), 4-way j-split ----
        if (tid < nd * 64) {
            int pr = tid >> 6, rem = tid & 63;
            int r = rem >> 2, sp = rem & 3;
            int p = s_i + pr;
            int len = i + 1;
            int j0 = (sp * len) >> 2, j1 = ((sp + 1) * len) >> 2;
            float acc = 0.f;
            const float* wrow = g_W1p + p * 128;
            const float* xr   = xs + r * XS;
            for (int j = j0; j < j1; ++j) acc = fmaf(wrow[j], xr[j], acc);
            acc += __shfl_xor_sync(0xffffffffu, acc, 1);
            acc += __shfl_xor_sync(0xffffffffu, acc, 2);
            if (sp == 0) h1T[r * PH + p] = fmaxf(g_b1p[p] + acc, 0.f);
        } else if (i < 126) {
            // idle threads: prefetch next step's weight rows
            if (tid >= 384) {                       // W3 row i+1 (4KB)
                const char* p = (const char*)((const ull*)g_W3z + (size_t)(i + 1) * 512)
                                + (tid - 384) * 32;
                asm volatile("prefetch.global.L1 [%0];" :: "l"(p));
            } else if (tid >= 256 && nd == 4 && s_n < 512) {  // next W2 rows (8KB)
                const char* p = (const char*)(g_W2q + (size_t)s_n * 512)
                                + (tid - 256) * 64;
                asm volatile("prefetch.global.L1 [%0];" :: "l"(p));
            }
        }
        __syncthreads();

        // ---- H2 phase: new layer-2 columns q in [s_i, s_n), S2-way p-split ----
        {
            const int S2 = (nd == 4) ? 8 : 4;       // uniform across block
            if (tid < nd * 16 * S2) {
                int qr, rem, r, sp;
                if (S2 == 8) { qr = tid >> 7; rem = tid & 127; r = rem >> 3; sp = rem & 7; }
                else         { qr = tid >> 6; rem = tid & 63;  r = rem >> 2; sp = rem & 3; }
                int q  = s_i + qr;
                int p0 = (sp * s_n) / S2, p1 = ((sp + 1) * s_n) / S2;
                float acc = 0.f;
                const float* wrow = g_W2q + q * 512;
                const float* hr   = h1T + r * PH;
#pragma unroll 4
                for (int p = p0; p < p1; ++p) acc = fmaf(wrow[p], hr[p], acc);
                acc += __shfl_xor_sync(0xffffffffu, acc, 1);
                acc += __shfl_xor_sync(0xffffffffu, acc, 2);
                if (S2 == 8) acc += __shfl_xor_sync(0xffffffffu, acc, 4);
                if (sp == 0) h2T[r * PH + q] = fmaxf(g_b2p[q] + acc, 0.f);
            }
        }
        __syncthreads();
    }

    __syncthreads();
    // coalesced writeout of x
    for (int t = tid; t < 16 * 128; t += THREADS) {
        int r = t >> 7, c = t & 127;
        out[(row0 + r) * 128 + c] = xs[r * XS + c];
    }
    if (lane == 0) out[2048 * 128 + row0 + w] = ldacc;
}

extern "C" void kernel_launch(void* const* d_in, const int* in_sizes, int n_in,
                              void* d_out, int out_size) {
    const float* u  = (const float*)d_in[0];
    const float* W1 = (const float*)d_in[1];
    const float* b1 = (const float*)d_in[2];
    const float* W2 = (const float*)d_in[3];
    const float* b2 = (const float*)d_in[4];
    const float* W3 = (const float*)d_in[5];
    const float* b3 = (const float*)d_in[6];
    const float* m1 = (const float*)d_in[7];
    const float* m2 = (const float*)d_in[8];
    const float* m3 = (const float*)d_in[9];
    float* out = (float*)d_out;

    const size_t smem = (size_t)(2 * 16 * PH + 2 * 16 * XS) * sizeof(float); // 83456 B
    cudaFuncSetAttribute(k_main, cudaFuncAttributeMaxDynamicSharedMemorySize, (int)smem);

    k_transform<<<256, 256>>>(W1, b1, W2, b2, W3, m1, m2, m3);
    k_main<<<128, THREADS, smem>>>(u, b3, out);
}

// round 10
// speedup vs baseline: 9.3990x; 1.0301x over previous
#include <cuda_runtime.h>
#include <math.h>

// IN_FEATURES=128, UNITS=512, BATCH=2048, out = [x (2048*128) ; logdet (2048)]
// O(n^2) MADE inverse, warp-per-row, zero CTA barriers in the main loop.
#define THREADS 512

typedef unsigned long long ull;

// ---- device scratch ----
__device__ float g_W1p[512 * 128];        // [p][j]  masked W1, hidden permuted
__device__ float g_W2q[512 * 512];        // [q][p]  masked W2, both permuted (scalar path)
__device__ float g_W2zf[256 * 512 * 2];   // [q/2][p]{q0,q1} paired columns
__device__ float g_W3zf[128 * 512 * 2];   // [o][q]{mu,sig} paired
__device__ float g_b1p[512];
__device__ float g_b2p[512];

__device__ __forceinline__ int posOf(int k) {
    int d = k % 127;
    int j = k / 127;
    return d * 4 + (d < 4 ? d : 4) + j;
}

// ---------------- prologue: mask + permute + repack ----------------
__global__ void k_transform(const float* __restrict__ W1, const float* __restrict__ b1,
                            const float* __restrict__ W2, const float* __restrict__ b2,
                            const float* __restrict__ W3,
                            const float* __restrict__ m1, const float* __restrict__ m2,
                            const float* __restrict__ m3) {
    int idx = blockIdx.x * blockDim.x + threadIdx.x;
    int stride = gridDim.x * blockDim.x;
    for (int t = idx; t < 512 * 128; t += stride) {
        int k = t >> 7, i = t & 127;
        g_W1p[posOf(k) * 128 + i] = W1[t] * m1[t];
    }
    for (int t = idx; t < 512 * 512; t += stride) {
        int m = t >> 9, k = t & 511;
        float v = W2[t] * m2[t];
        int q = posOf(m), p = posOf(k);
        g_W2q[q * 512 + p] = v;
        g_W2zf[((q >> 1) * 512 + p) * 2 + (q & 1)] = v;
    }
    for (int t = idx; t < 256 * 512; t += stride) {
        int o = t >> 9, m = t & 511;
        float v = W3[t] * m3[t];
        int q = posOf(m);
        if (o < 128) g_W3zf[(o * 512 + q) * 2]             = v;
        else         g_W3zf[((o - 128) * 512 + q) * 2 + 1] = v;
    }
    for (int t = idx; t < 512; t += stride) {
        g_b1p[posOf(t)] = b1[t];
        g_b2p[posOf(t)] = b2[t];
    }
}

// ---- packed f32x2 helpers ----
__device__ __forceinline__ ull dup2(float w) {
    ull r; asm("mov.b64 %0, {%1, %1};" : "=l"(r) : "f"(w)); return r;
}
__device__ __forceinline__ float2 u2f(ull v) {
    float2 f; asm("mov.b64 {%0, %1}, %2;" : "=f"(f.x), "=f"(f.y) : "l"(v)); return f;
}
#define PFMA(acc, w, v) asm("fma.rn.f32x2 %0, %1, %2, %0;" : "+l"(acc) : "l"(w), "l"(v))
__device__ __forceinline__ void addp(ull& a, ull b) {
    asm("add.rn.f32x2 %0, %0, %1;" : "+l"(a) : "l"(b));
}

// smem per-row layout (floats)
#define OFF_H1 0
#define OFF_H2 512
#define OFF_X  1024
#define OFF_U  1160
#define SR     1296      // row stride: 16 rows * 1296 * 4B = 82944 B

// ---------------- main kernel: 128 CTAs x 16 warps, warp = row ----------------
__global__ void __launch_bounds__(THREADS, 1)
k_main(const float* __restrict__ u, const float* __restrict__ b3,
       float* __restrict__ out) {
    extern __shared__ float sm[];
    const int tid  = threadIdx.x;
    const int lane = tid & 31;
    const int w    = tid >> 5;          // warp id == local row
    const int row0 = blockIdx.x * 16;

    float* h1 = sm + w * SR + OFF_H1;
    float* h2 = sm + w * SR + OFF_H2;
    float* xr = sm + w * SR + OFF_X;
    float* ur = sm + w * SR + OFF_U;

    // stage u (block-wide, single barrier before the loop)
    for (int t = tid; t < 16 * 128; t += THREADS) {
        int r = t >> 7, c = t & 127;
        sm[r * SR + OFF_U + c] = u[(row0 + r) * 128 + c];
    }
    float ldacc = 0.f;
    __syncthreads();

    const ull* W3z = (const ull*)g_W3zf;
    const ull* W2z = (const ull*)g_W2zf;

    for (int i = 0; i < 128; ++i) {
        const int s_i = 4 * i + (i < 4 ? i : 4);

        // ---- Z: (mu_i, sigma_i) packed dot over h2 prefix ----
        {
            ull acc = 0ull;
            const ull* wz = W3z + (size_t)i * 512;
            for (int q = lane; q < s_i; q += 32)
                PFMA(acc, wz[q], dup2(h2[q]));
#pragma unroll
            for (int off = 16; off >= 1; off >>= 1)
                addp(acc, __shfl_xor_sync(0xffffffffu, acc, off));
            float2 ms = u2f(acc);
            float sg = ms.y + __ldg(&b3[i + 128]);
            float xv = ur[i] * __expf(sg) + (ms.x + __ldg(&b3[i]));
            if (lane == 0) { xr[i] = xv; ldacc += sg; }
        }
        __syncwarp();
        if (i == 127) break;

        const int nd  = (i < 4) ? 5 : 4;
        const int s_n = s_i + nd;

        // ---- H1: new layer-1 columns, 8 lanes per column ----
        // UNIFORM trip count: all 32 lanes run ceil(nd/4) iterations; shuffles
        // are executed by the full warp every iteration; writes are guarded.
        {
            int g  = lane >> 3;         // column group 0..3
            int sp = lane & 7;          // split within column
            int nIter = (nd + 3) >> 2;  // 1 (nd=4) or 2 (nd=5)
            for (int cc = 0; cc < nIter; ++cc) {
                int c  = cc * 4 + g;
                int cA = c < nd ? c : nd - 1;     // clamped (pad lanes redo last col)
                int p  = s_i + cA;
                const float* w1row = g_W1p + p * 128;
                float a = 0.f;
                for (int j = sp; j <= i; j += 8)
                    a = fmaf(w1row[j], xr[j], a);
                a += __shfl_xor_sync(0xffffffffu, a, 1);
                a += __shfl_xor_sync(0xffffffffu, a, 2);
                a += __shfl_xor_sync(0xffffffffu, a, 4);
                if (sp == 0 && c < nd) h1[p] = fmaxf(g_b1p[p] + a, 0.f);
            }
        }
        __syncwarp();

        // ---- H2: new layer-2 columns ----
        if (i >= 4) {
            // packed pairs: s_i even, nd=4 -> pairs (s_i,s_i+1), (s_i+2,s_i+3)
            int h  = lane >> 4;           // pair index 0/1
            int sp = lane & 15;
            const ull* w2p = W2z + ((size_t)(s_i >> 1) + h) * 512;
            ull a = 0ull;
            for (int p = sp; p < s_n; p += 16)
                PFMA(a, w2p[p], dup2(h1[p]));
#pragma unroll
            for (int off = 8; off >= 1; off >>= 1)
                addp(a, __shfl_xor_sync(0xffffffffu, a, off));
            if (sp == 0) {
                float2 v = u2f(a);
                int q0 = s_i + 2 * h;
                h2[q0]     = fmaxf(g_b2p[q0] + v.x, 0.f);
                h2[q0 + 1] = fmaxf(g_b2p[q0 + 1] + v.y, 0.f);
            }
        } else {
            // scalar fallback (i<4, odd s_i): 8 lanes per column, uniform trips
            int g  = lane >> 3;
            int sp = lane & 7;
            int nIter = (nd + 3) >> 2;    // nd=5 -> 2
            for (int cc = 0; cc < nIter; ++cc) {
                int c  = cc * 4 + g;
                int cA = c < nd ? c : nd - 1;
                int q  = s_i + cA;
                const float* w2row = g_W2q + q * 512;
                float a = 0.f;
                for (int p = sp; p < s_n; p += 8)
                    a = fmaf(w2row[p], h1[p], a);
                a += __shfl_xor_sync(0xffffffffu, a, 1);
                a += __shfl_xor_sync(0xffffffffu, a, 2);
                a += __shfl_xor_sync(0xffffffffu, a, 4);
                if (sp == 0 && c < nd) h2[q] = fmaxf(g_b2p[q] + a, 0.f);
            }
        }
        __syncwarp();
    }

    if (lane == 0) out[2048 * 128 + row0 + w] = ldacc;

    __syncthreads();
    // coalesced writeout of x
    for (int t = tid; t < 16 * 128; t += THREADS) {
        int r = t >> 7, c = t & 127;
        out[(row0 + r) * 128 + c] = sm[r * SR + OFF_X + c];
    }
}

extern "C" void kernel_launch(void* const* d_in, const int* in_sizes, int n_in,
                              void* d_out, int out_size) {
    const float* u  = (const float*)d_in[0];
    const float* W1 = (const float*)d_in[1];
    const float* b1 = (const float*)d_in[2];
    const float* W2 = (const float*)d_in[3];
    const float* b2 = (const float*)d_in[4];
    const float* W3 = (const float*)d_in[5];
    const float* b3 = (const float*)d_in[6];
    const float* m1 = (const float*)d_in[7];
    const float* m2 = (const float*)d_in[8];
    const float* m3 = (const float*)d_in[9];
    float* out = (float*)d_out;

    const size_t smem = (size_t)(16 * SR) * sizeof(float); // 82944 B
    cudaFuncSetAttribute(k_main, cudaFuncAttributeMaxDynamicSharedMemorySize, (int)smem);

    k_transform<<<256, 256>>>(W1, b1, W2, b2, W3, m1, m2, m3);
    k_main<<<128, THREADS, smem>>>(u, b3, out);
}

// round 12
// speedup vs baseline: 19.8231x; 2.1091x over previous
#include <cuda_runtime.h>
#include <math.h>

// IN_FEATURES=128, UNITS=512, BATCH=2048, out = [x (2048*128) ; logdet (2048)]
// O(n^2) MADE inverse, warp-per-row, software-pipelined inner loops.
#define THREADS 512

typedef unsigned long long ull;

// ---- device scratch ----
__device__ float g_W1p[512 * 128];        // [p][j]  masked W1, hidden permuted
__device__ float g_W2q[512 * 512];        // [q][p]  masked W2 (scalar path)
__device__ float g_W2zf[256 * 512 * 2];   // [q/2][p]{q0,q1} paired columns
__device__ float g_W3zf[128 * 512 * 2];   // [o][q]{mu,sig} paired
__device__ float g_b1p[512];
__device__ float g_b2p[512];

__device__ __forceinline__ int posOf(int k) {
    int d = k % 127;
    int j = k / 127;
    return d * 4 + (d < 4 ? d : 4) + j;
}

// ---------------- prologue: mask + permute + repack ----------------
__global__ void k_transform(const float* __restrict__ W1, const float* __restrict__ b1,
                            const float* __restrict__ W2, const float* __restrict__ b2,
                            const float* __restrict__ W3,
                            const float* __restrict__ m1, const float* __restrict__ m2,
                            const float* __restrict__ m3) {
    int idx = blockIdx.x * blockDim.x + threadIdx.x;
    int stride = gridDim.x * blockDim.x;
    for (int t = idx; t < 512 * 128; t += stride) {
        int k = t >> 7, i = t & 127;
        g_W1p[posOf(k) * 128 + i] = W1[t] * m1[t];
    }
    for (int t = idx; t < 512 * 512; t += stride) {
        int m = t >> 9, k = t & 511;
        float v = W2[t] * m2[t];
        int q = posOf(m), p = posOf(k);
        g_W2q[q * 512 + p] = v;
        g_W2zf[((q >> 1) * 512 + p) * 2 + (q & 1)] = v;
    }
    for (int t = idx; t < 256 * 512; t += stride) {
        int o = t >> 9, m = t & 511;
        float v = W3[t] * m3[t];
        int q = posOf(m);
        if (o < 128) g_W3zf[(o * 512 + q) * 2]             = v;
        else         g_W3zf[((o - 128) * 512 + q) * 2 + 1] = v;
    }
    for (int t = idx; t < 512; t += stride) {
        g_b1p[posOf(t)] = b1[t];
        g_b2p[posOf(t)] = b2[t];
    }
}

// ---- packed f32x2 helpers ----
__device__ __forceinline__ ull dup2(float w) {
    ull r; asm("mov.b64 %0, {%1, %1};" : "=l"(r) : "f"(w)); return r;
}
__device__ __forceinline__ float2 u2f(ull v) {
    float2 f; asm("mov.b64 {%0, %1}, %2;" : "=f"(f.x), "=f"(f.y) : "l"(v)); return f;
}
__device__ __forceinline__ void pfma(ull& acc, ull w, ull v) {
    asm("fma.rn.f32x2 %0, %1, %2, %0;" : "+l"(acc) : "l"(w), "l"(v));
}
__device__ __forceinline__ void addp(ull& a, ull b) {
    asm("add.rn.f32x2 %0, %0, %1;" : "+l"(a) : "l"(b));
}

// smem per-row layout (floats)
#define OFF_H1 0
#define OFF_H2 512
#define OFF_X  1024
#define OFF_U  1152
#define SR     1288      // row stride (floats)

// ---------------- main kernel: 128 CTAs x 16 warps, warp = row ----------------
__global__ void __launch_bounds__(THREADS, 1)
k_main(const float* __restrict__ u, const float* __restrict__ b3,
       float* __restrict__ out) {
    extern __shared__ float sm[];
    float* b3s = sm + 16 * SR;          // 256 floats
    const int tid  = threadIdx.x;
    const int lane = tid & 31;
    const int w    = tid >> 5;          // warp id == local row
    const int row0 = blockIdx.x * 16;

    float* h1 = sm + w * SR + OFF_H1;
    float* h2 = sm + w * SR + OFF_H2;
    float* xr = sm + w * SR + OFF_X;
    float* ur = sm + w * SR + OFF_U;

    for (int t = tid; t < 16 * 128; t += THREADS) {
        int r = t >> 7, c = t & 127;
        sm[r * SR + OFF_U + c] = u[(row0 + r) * 128 + c];
    }
    if (tid < 256) b3s[tid] = b3[tid];
    float ldacc = 0.f;
    __syncthreads();

    const ull* W3z = (const ull*)g_W3zf;
    const ull* W2z = (const ull*)g_W2zf;

    for (int i = 0; i < 128; ++i) {
        const int s_i = 4 * i + (i < 4 ? i : 4);

        // ---- Z: (mu_i, sigma_i) packed dot over h2 prefix, batched x8 ----
        {
            ull acc0 = 0ull, acc1 = 0ull;
            const ull* wz = W3z + (size_t)i * 512;
            const int nIt = (s_i + 31) >> 5;          // <= 16
            for (int it = 0; it < nIt; it += 8) {
                ull  wv[8]; float hv[8];
#pragma unroll
                for (int b = 0; b < 8; ++b) {
                    int q = lane + ((it + b) << 5);
                    bool ok = q < s_i;
                    wv[b] = ok ? __ldg(wz + q) : 0ull;
                    hv[b] = ok ? h2[q] : 0.f;
                }
#pragma unroll
                for (int b = 0; b < 8; ++b) {
                    ull& acc = (b & 1) ? acc1 : acc0;
                    pfma(acc, wv[b], dup2(hv[b]));
                }
            }
            addp(acc0, acc1);
#pragma unroll
            for (int off = 16; off >= 1; off >>= 1)
                addp(acc0, __shfl_xor_sync(0xffffffffu, acc0, off));
            float2 ms = u2f(acc0);
            float sg = ms.y + b3s[i + 128];
            float xv = ur[i] * __expf(sg) + (ms.x + b3s[i]);
            if (lane == 0) { xr[i] = xv; ldacc += sg; }
        }
        __syncwarp();
        if (i == 127) break;

        const int nd  = (i < 4) ? 5 : 4;
        const int s_n = s_i + nd;

        // ---- H1: new layer-1 columns, 8 lanes/col, batched x8 ----
        {
            int g  = lane >> 3;
            int sp = lane & 7;
            int len = i + 1;
            int nIt = (len + 7) >> 3;                 // <= 16
            int nCols = (nd + 3) >> 2;                // 1 or 2 (uniform)
            for (int cc = 0; cc < nCols; ++cc) {
                int c  = cc * 4 + g;
                int cA = c < nd ? c : nd - 1;
                int p  = s_i + cA;
                const float* w1row = g_W1p + p * 128;
                float a0 = 0.f, a1 = 0.f;
                for (int it = 0; it < nIt; it += 8) {
                    float wv[8], xv[8];
#pragma unroll
                    for (int b = 0; b < 8; ++b) {
                        int j = sp + ((it + b) << 3);
                        bool ok = j < len;
                        wv[b] = ok ? __ldg(w1row + j) : 0.f;
                        xv[b] = ok ? xr[j] : 0.f;
                    }
#pragma unroll
                    for (int b = 0; b < 8; ++b) {
                        if (b & 1) a1 = fmaf(wv[b], xv[b], a1);
                        else       a0 = fmaf(wv[b], xv[b], a0);
                    }
                }
                float a = a0 + a1;
                a += __shfl_xor_sync(0xffffffffu, a, 1);
                a += __shfl_xor_sync(0xffffffffu, a, 2);
                a += __shfl_xor_sync(0xffffffffu, a, 4);
                if (sp == 0 && c < nd) h1[p] = fmaxf(g_b1p[p] + a, 0.f);
            }
        }
        __syncwarp();

        // ---- H2: new layer-2 columns ----
        if (i >= 4) {
            // packed pairs, 16 lanes/pair, batched x8
            int h  = lane >> 4;
            int sp = lane & 15;
            const ull* w2p = W2z + ((size_t)(s_i >> 1) + h) * 512;
            ull acc0 = 0ull, acc1 = 0ull;
            const int nIt = (s_n + 15) >> 4;          // <= 32
            for (int it = 0; it < nIt; it += 8) {
                ull wv[8]; float hv[8];
#pragma unroll
                for (int b = 0; b < 8; ++b) {
                    int p = sp + ((it + b) << 4);
                    bool ok = p < s_n;
                    wv[b] = ok ? __ldg(w2p + p) : 0ull;
                    hv[b] = ok ? h1[p] : 0.f;
                }
#pragma unroll
                for (int b = 0; b < 8; ++b) {
                    ull& acc = (b & 1) ? acc1 : acc0;
                    pfma(acc, wv[b], dup2(hv[b]));
                }
            }
            addp(acc0, acc1);
#pragma unroll
            for (int off = 8; off >= 1; off >>= 1)
                addp(acc0, __shfl_xor_sync(0xffffffffu, acc0, off));
            if (sp == 0) {
                float2 v = u2f(acc0);
                int q0 = s_i + 2 * h;
                h2[q0]     = fmaxf(g_b2p[q0] + v.x, 0.f);
                h2[q0 + 1] = fmaxf(g_b2p[q0 + 1] + v.y, 0.f);
            }
        } else {
            // scalar fallback (i<4): 8 lanes/col, batched x4 (s_n <= 20)
            int g  = lane >> 3;
            int sp = lane & 7;
            int nIter = (nd + 3) >> 2;
            for (int cc = 0; cc < nIter; ++cc) {
                int c  = cc * 4 + g;
                int cA = c < nd ? c : nd - 1;
                int q  = s_i + cA;
                const float* w2row = g_W2q + q * 512;
                float a0 = 0.f, a1 = 0.f;
                const int nIt = (s_n + 7) >> 3;       // <= 3
                for (int it = 0; it < nIt; it += 4) {
                    float wv[4], hv[4];
#pragma unroll
                    for (int b = 0; b < 4; ++b) {
                        int p = sp + ((it + b) << 3);
                        bool ok = p < s_n;
                        wv[b] = ok ? __ldg(w2row + p) : 0.f;
                        hv[b] = ok ? h1[p] : 0.f;
                    }
#pragma unroll
                    for (int b = 0; b < 4; ++b) {
                        if (b & 1) a1 = fmaf(wv[b], hv[b], a1);
                        else       a0 = fmaf(wv[b], hv[b], a0);
                    }
                }
                float a = a0 + a1;
                a += __shfl_xor_sync(0xffffffffu, a, 1);
                a += __shfl_xor_sync(0xffffffffu, a, 2);
                a += __shfl_xor_sync(0xffffffffu, a, 4);
                if (sp == 0 && c < nd) h2[q] = fmaxf(g_b2p[q] + a, 0.f);
            }
        }
        __syncwarp();
    }

    if (lane == 0) out[2048 * 128 + row0 + w] = ldacc;

    __syncthreads();
    for (int t = tid; t < 16 * 128; t += THREADS) {
        int r = t >> 7, c = t & 127;
        out[(row0 + r) * 128 + c] = sm[r * SR + OFF_X + c];
    }
}

extern "C" void kernel_launch(void* const* d_in, const int* in_sizes, int n_in,
                              void* d_out, int out_size) {
    const float* u  = (const float*)d_in[0];
    const float* W1 = (const float*)d_in[1];
    const float* b1 = (const float*)d_in[2];
    const float* W2 = (const float*)d_in[3];
    const float* b2 = (const float*)d_in[4];
    const float* W3 = (const float*)d_in[5];
    const float* b3 = (const float*)d_in[6];
    const float* m1 = (const float*)d_in[7];
    const float* m2 = (const float*)d_in[8];
    const float* m3 = (const float*)d_in[9];
    float* out = (float*)d_out;

    const size_t smem = (size_t)(16 * SR + 256) * sizeof(float); // 83456 B
    cudaFuncSetAttribute(k_main, cudaFuncAttributeMaxDynamicSharedMemorySize, (int)smem);

    k_transform<<<256, 256>>>(W1, b1, W2, b2, W3, m1, m2, m3);
    k_main<<<128, THREADS, smem>>>(u, b3, out);
}

// round 13
// speedup vs baseline: 21.4564x; 1.0824x over previous
#include <cuda_runtime.h>
#include <math.h>

// IN_FEATURES=128, UNITS=512, BATCH=2048, out = [x (2048*128) ; logdet (2048)]
// O(n^2) MADE inverse, warp-per-row, vectorized + predication-free inner loops
// (masked weights are zero outside each prefix; smem state zero-initialized).
#define THREADS 512

typedef unsigned long long ull;

// ---- device scratch ----
__device__ float g_W1p[512 * 128];        // [p][j]  masked W1, hidden permuted
__device__ float g_W2q[512 * 512];        // [q][p]  masked W2 (scalar path, i<4)
__device__ float g_W2zf[256 * 512 * 2];   // [q/2][p]{q0,q1} paired columns
__device__ float g_W3zf[128 * 512 * 2];   // [o][q]{mu,sig} paired
__device__ float g_b1p[512];
__device__ float g_b2p[512];

__device__ __forceinline__ int posOf(int k) {
    int d = k % 127;
    int j = k / 127;
    return d * 4 + (d < 4 ? d : 4) + j;
}

// ---------------- prologue: mask + permute + repack ----------------
__global__ void k_transform(const float* __restrict__ W1, const float* __restrict__ b1,
                            const float* __restrict__ W2, const float* __restrict__ b2,
                            const float* __restrict__ W3,
                            const float* __restrict__ m1, const float* __restrict__ m2,
                            const float* __restrict__ m3) {
    int idx = blockIdx.x * blockDim.x + threadIdx.x;
    int stride = gridDim.x * blockDim.x;
    for (int t = idx; t < 512 * 128; t += stride) {
        int k = t >> 7, i = t & 127;
        g_W1p[posOf(k) * 128 + i] = W1[t] * m1[t];
    }
    for (int t = idx; t < 512 * 512; t += stride) {
        int m = t >> 9, k = t & 511;
        float v = W2[t] * m2[t];
        int q = posOf(m), p = posOf(k);
        g_W2q[q * 512 + p] = v;
        g_W2zf[((q >> 1) * 512 + p) * 2 + (q & 1)] = v;
    }
    for (int t = idx; t < 256 * 512; t += stride) {
        int o = t >> 9, m = t & 511;
        float v = W3[t] * m3[t];
        int q = posOf(m);
        if (o < 128) g_W3zf[(o * 512 + q) * 2]             = v;
        else         g_W3zf[((o - 128) * 512 + q) * 2 + 1] = v;
    }
    for (int t = idx; t < 512; t += stride) {
        g_b1p[posOf(t)] = b1[t];
        g_b2p[posOf(t)] = b2[t];
    }
}

// ---- packed f32x2 helpers ----
__device__ __forceinline__ ull dup2(float w) {
    ull r; asm("mov.b64 %0, {%1, %1};" : "=l"(r) : "f"(w)); return r;
}
__device__ __forceinline__ ull mk2(unsigned lo, unsigned hi) {
    ull r; asm("mov.b64 %0, {%1, %2};" : "=l"(r) : "r"(lo), "r"(hi)); return r;
}
__device__ __forceinline__ float2 u2f(ull v) {
    float2 f; asm("mov.b64 {%0, %1}, %2;" : "=f"(f.x), "=f"(f.y) : "l"(v)); return f;
}
__device__ __forceinline__ void pfma(ull& acc, ull w, ull v) {
    asm("fma.rn.f32x2 %0, %1, %2, %0;" : "+l"(acc) : "l"(w), "l"(v));
}
__device__ __forceinline__ void addp(ull& a, ull b) {
    asm("add.rn.f32x2 %0, %0, %1;" : "+l"(a) : "l"(b));
}

// smem per-row layout (floats)
#define OFF_H1 0
#define OFF_H2 512
#define OFF_X  1024
#define OFF_U  1152
#define SR     1288      // row stride (floats); 1288*4 divisible by 16

// ---------------- main kernel: 128 CTAs x 16 warps, warp = row ----------------
__global__ void __launch_bounds__(THREADS, 1)
k_main(const float* __restrict__ u, const float* __restrict__ b3,
       float* __restrict__ out) {
    extern __shared__ float sm[];
    float* b3s = sm + 16 * SR;          // 256 floats
    const int tid  = threadIdx.x;
    const int lane = tid & 31;
    const int w    = tid >> 5;          // warp id == local row
    const int row0 = blockIdx.x * 16;

    float* h1 = sm + w * SR + OFF_H1;
    float* h2 = sm + w * SR + OFF_H2;
    float* xr = sm + w * SR + OFF_X;
    float* ur = sm + w * SR + OFF_U;

    // zero h1/h2/x (so 0-weight x garbage never poisons accumulators)
    for (int t = tid; t < 16 * 1152; t += THREADS) {
        int r = t / 1152, o = t - r * 1152;
        sm[r * SR + o] = 0.f;
    }
    for (int t = tid; t < 16 * 128; t += THREADS) {
        int r = t >> 7, c = t & 127;
        sm[r * SR + OFF_U + c] = u[(row0 + r) * 128 + c];
    }
    if (tid < 256) b3s[tid] = b3[tid];
    float ldacc = 0.f;
    __syncthreads();

    const ull* W2z = (const ull*)g_W2zf;

    for (int i = 0; i < 128; ++i) {
        const int s_i = 4 * i + (i < 4 ? i : 4);

        // ---- Z: (mu_i, sigma_i); lane handles q-pair, groups of 4 passes ----
        {
            ull acc0 = 0ull, acc1 = 0ull;
            const uint4* wz4 = (const uint4*)((const ull*)g_W3zf + (size_t)i * 512);
            const int nG = (s_i + 255) >> 8;   // <= 2
            for (int g = 0; g < nG; ++g) {
                uint4 wv[4]; float2 hv[4];
#pragma unroll
                for (int b = 0; b < 4; ++b) {
                    int idx = lane + ((g * 4 + b) << 5);
                    wv[b] = __ldg(wz4 + idx);
                    hv[b] = *(const float2*)(h2 + 2 * idx);
                }
#pragma unroll
                for (int b = 0; b < 4; ++b) {
                    pfma(acc0, mk2(wv[b].x, wv[b].y), dup2(hv[b].x));
                    pfma(acc1, mk2(wv[b].z, wv[b].w), dup2(hv[b].y));
                }
            }
            addp(acc0, acc1);
#pragma unroll
            for (int off = 16; off >= 1; off >>= 1)
                addp(acc0, __shfl_xor_sync(0xffffffffu, acc0, off));
            float2 ms = u2f(acc0);
            float sg = ms.y + b3s[i + 128];
            float xv = ur[i] * __expf(sg) + (ms.x + b3s[i]);
            if (lane == 0) { xr[i] = xv; ldacc += sg; }
        }
        __syncwarp();
        if (i == 127) break;

        const int nd  = (i < 4) ? 5 : 4;
        const int s_n = s_i + nd;

        // ---- H1: new layer-1 cols; 8 lanes/col, lane = float4 of j ----
        {
            int g8 = lane >> 3, sp = lane & 7;
            int len = i + 1;
            int nG = (len + 63) >> 6;              // <= 2 (groups of 2 float4-passes)
            int nCols = (nd + 3) >> 2;             // 1 or 2 (uniform)
            const float4* xr4 = (const float4*)xr;
            for (int cc = 0; cc < nCols; ++cc) {
                int c  = cc * 4 + g8;
                int cA = c < nd ? c : nd - 1;
                int p  = s_i + cA;
                const float4* w1r = (const float4*)(g_W1p + p * 128);
                float a0 = 0.f, a1 = 0.f;
                for (int g = 0; g < nG; ++g) {
                    float4 wv[2], xv[2];
#pragma unroll
                    for (int b = 0; b < 2; ++b) {
                        int idx = sp + ((g * 2 + b) << 3);
                        wv[b] = __ldg(w1r + idx);
                        xv[b] = xr4[idx];
                    }
#pragma unroll
                    for (int b = 0; b < 2; ++b) {
                        a0 = fmaf(wv[b].x, xv[b].x, a0);
                        a1 = fmaf(wv[b].y, xv[b].y, a1);
                        a0 = fmaf(wv[b].z, xv[b].z, a0);
                        a1 = fmaf(wv[b].w, xv[b].w, a1);
                    }
                }
                float a = a0 + a1;
                a += __shfl_xor_sync(0xffffffffu, a, 1);
                a += __shfl_xor_sync(0xffffffffu, a, 2);
                a += __shfl_xor_sync(0xffffffffu, a, 4);
                if (sp == 0 && c < nd) h1[p] = fmaxf(g_b1p[p] + a, 0.f);
            }
        }
        __syncwarp();

        // ---- H2: new layer-2 cols ----
        if (i >= 4) {
            // q-pairs; 16 lanes/pair; lane = p-pair (uint4 weights, float2 h1)
            int h  = lane >> 4;
            int sp = lane & 15;
            const uint4* w2r = (const uint4*)(W2z + ((size_t)(s_i >> 1) + h) * 512);
            ull acc0 = 0ull, acc1 = 0ull;
            const int nG = (s_n + 127) >> 7;       // <= 4 (groups of 4 passes)
            for (int g = 0; g < nG; ++g) {
                uint4 wv[4]; float2 hv[4];
#pragma unroll
                for (int b = 0; b < 4; ++b) {
                    int idx = sp + ((g * 4 + b) << 4);
                    wv[b] = __ldg(w2r + idx);
                    hv[b] = *(const float2*)(h1 + 2 * idx);
                }
#pragma unroll
                for (int b = 0; b < 4; ++b) {
                    pfma(acc0, mk2(wv[b].x, wv[b].y), dup2(hv[b].x));
                    pfma(acc1, mk2(wv[b].z, wv[b].w), dup2(hv[b].y));
                }
            }
            addp(acc0, acc1);
#pragma unroll
            for (int off = 8; off >= 1; off >>= 1)
                addp(acc0, __shfl_xor_sync(0xffffffffu, acc0, off));
            if (sp == 0) {
                float2 v = u2f(acc0);
                int q0 = s_i + 2 * h;
                h2[q0]     = fmaxf(g_b2p[q0] + v.x, 0.f);
                h2[q0 + 1] = fmaxf(g_b2p[q0 + 1] + v.y, 0.f);
            }
        } else {
            // scalar fallback (i<4, s_n<=20): 8 lanes/col, 3 fixed batches
            int g8 = lane >> 3, sp = lane & 7;
            int nIter = (nd + 3) >> 2;
            for (int cc = 0; cc < nIter; ++cc) {
                int c  = cc * 4 + g8;
                int cA = c < nd ? c : nd - 1;
                int q  = s_i + cA;
                const float* w2row = g_W2q + q * 512;
                float a = 0.f;
#pragma unroll
                for (int b = 0; b < 3; ++b) {
                    int p = sp + (b << 3);
                    a = fmaf(__ldg(w2row + p), h1[p], a);
                }
                a += __shfl_xor_sync(0xffffffffu, a, 1);
                a += __shfl_xor_sync(0xffffffffu, a, 2);
                a += __shfl_xor_sync(0xffffffffu, a, 4);
                if (sp == 0 && c < nd) h2[q] = fmaxf(g_b2p[q] + a, 0.f);
            }
        }
        __syncwarp();
    }

    if (lane == 0) out[2048 * 128 + row0 + w] = ldacc;

    __syncthreads();
    for (int t = tid; t < 16 * 128; t += THREADS) {
        int r = t >> 7, c = t & 127;
        out[(row0 + r) * 128 + c] = sm[r * SR + OFF_X + c];
    }
}

extern "C" void kernel_launch(void* const* d_in, const int* in_sizes, int n_in,
                              void* d_out, int out_size) {
    const float* u  = (const float*)d_in[0];
    const float* W1 = (const float*)d_in[1];
    const float* b1 = (const float*)d_in[2];
    const float* W2 = (const float*)d_in[3];
    const float* b2 = (const float*)d_in[4];
    const float* W3 = (const float*)d_in[5];
    const float* b3 = (const float*)d_in[6];
    const float* m1 = (const float*)d_in[7];
    const float* m2 = (const float*)d_in[8];
    const float* m3 = (const float*)d_in[9];
    float* out = (float*)d_out;

    const size_t smem = (size_t)(16 * SR + 256) * sizeof(float); // 83456 B
    cudaFuncSetAttribute(k_main, cudaFuncAttributeMaxDynamicSharedMemorySize, (int)smem);

    k_transform<<<256, 256>>>(W1, b1, W2, b2, W3, m1, m2, m3);
    k_main<<<128, THREADS, smem>>>(u, b3, out);
}